// round 8
// baseline (speedup 1.0000x reference)
#include <cuda_runtime.h>
#include <cuda_bf16.h>
#include <cstdint>

#define TOKENS 2048
#define HIDDEN 4096
#define OUTDIM 4096
#define NLORA  16
#define RANK   16
#define KEXT   (HIDDEN + NLORA * RANK)   // 4352
#define KG16   (KEXT / 16)               // 272

#define BM 256
#define BN 64
#define BK 64
#define NCH (KEXT / BK)                  // 68

#define STRIDE 80                        // 64B data + 16B pad (conflict-free ldmatrix)
#define OFF_AHI 0
#define OFF_ALO (BM * STRIDE)                       // 20480
#define OFF_BHI (2 * BM * STRIDE)                   // 40960
#define OFF_BLO (2 * BM * STRIDE + BN * STRIDE)     // 46080
#define STG     (2 * BM * STRIDE + 2 * BN * STRIDE) // 51200
#define SMEM_BYTES (3 * STG)                        // 153600

// quantized operand buffers (int8), one flat array
#define QXH 0u
#define QXL ((uint32_t)TOKENS * KEXT)
#define QWH ((uint32_t)(2 * TOKENS) * KEXT)
#define QWL ((uint32_t)(2 * TOKENS) * KEXT + (uint32_t)OUTDIM * KEXT)
__device__ __align__(16) int8_t g_q[(size_t)(2 * TOKENS + 2 * OUTDIM) * KEXT];
__device__ float g_ax[TOKENS * RANK];
__device__ unsigned g_smax[2];           // abs-max bits: [0]=x side, [1]=w side
__device__ int g_idx64;

// ---------------- helpers ----------------
__device__ __forceinline__ uint32_t smem_u32(const void* p) {
    uint32_t a;
    asm("{ .reg .u64 t; cvta.to.shared.u64 t, %1; cvt.u32.u64 %0, t; }" : "=r"(a) : "l"(p));
    return a;
}
__device__ __forceinline__ void cp16(uint32_t sdst, const void* gsrc) {
    asm volatile("cp.async.cg.shared.global [%0], [%1], 16;" :: "r"(sdst), "l"(gsrc) : "memory");
}
#define CP_COMMIT() asm volatile("cp.async.commit_group;" ::: "memory")

#define LDSM4(r, a) \
    asm volatile("ldmatrix.sync.aligned.m8n8.x4.shared.b16 {%0,%1,%2,%3}, [%4];" \
        : "=r"((r)[0]), "=r"((r)[1]), "=r"((r)[2]), "=r"((r)[3]) : "r"(a))

__device__ __forceinline__ void imma(int* c, const uint32_t* a, uint32_t b0, uint32_t b1) {
    asm volatile(
        "mma.sync.aligned.m16n8k32.row.col.s32.s8.s8.s32 "
        "{%0,%1,%2,%3}, {%4,%5,%6,%7}, {%8,%9}, {%0,%1,%2,%3};"
        : "+r"(c[0]), "+r"(c[1]), "+r"(c[2]), "+r"(c[3])
        : "r"(a[0]), "r"(a[1]), "r"(a[2]), "r"(a[3]), "r"(b0), "r"(b1));
}

// split v into h*128 + l with |q| <= 16256, l in [-64,63]
__device__ __forceinline__ void quant15(float v, float inv, int8_t* h, int8_t* l) {
    int q = __float2int_rn(v * inv);
    int hh = (q + 64) >> 7;
    *h = (int8_t)hh;
    *l = (int8_t)(q - (hh << 7));
}

// ---------------- prep: zero scale slots ----------------
__global__ void init_kernel() {
    if (threadIdx.x < 2) g_smax[threadIdx.x] = 0u;
}

// ---------------- prep: detect int32 vs int64 indices ----------------
__global__ void detect_kernel(const int* __restrict__ w) {
    __shared__ int any;
    if (threadIdx.x == 0) any = 0;
    __syncthreads();
    for (int i = threadIdx.x * 2 + 1; i < TOKENS; i += 2 * blockDim.x)
        if (w[i] != 0) any = 1;
    __syncthreads();
    if (threadIdx.x == 0) g_idx64 = (any == 0) ? 1 : 0;
}

// ---------------- prep: abs-max reduction into g_smax[slot] ----------------
__global__ void maxabs_kernel(const float4* __restrict__ p, int n4, int slot) {
    float m = 0.f;
    for (int i = blockIdx.x * blockDim.x + threadIdx.x; i < n4; i += gridDim.x * blockDim.x) {
        float4 v = p[i];
        m = fmaxf(m, fmaxf(fmaxf(fabsf(v.x), fabsf(v.y)), fmaxf(fabsf(v.z), fabsf(v.w))));
    }
#pragma unroll
    for (int o = 16; o > 0; o >>= 1) m = fmaxf(m, __shfl_xor_sync(0xffffffffu, m, o));
    __shared__ float red[8];
    if ((threadIdx.x & 31) == 0) red[threadIdx.x >> 5] = m;
    __syncthreads();
    if (threadIdx.x == 0) {
        float mm = 0.f;
        for (int i = 0; i < (int)(blockDim.x >> 5); i++) mm = fmaxf(mm, red[i]);
        atomicMax(&g_smax[slot], __float_as_uint(mm));
    }
}

// ---------------- prep: per-token rank-16 projection (fp32) + max ----------------
__global__ void lora_proj_kernel(const float* __restrict__ x,
                                 const float* __restrict__ la,
                                 const void* __restrict__ idx_raw) {
    const int t = blockIdx.x;
    int idx;
    if (g_idx64) idx = (int)((const long long*)idx_raw)[t];
    else         idx = ((const int*)idx_raw)[t];
    if (idx < 0 || idx >= NLORA) return;

    const float4* xr = reinterpret_cast<const float4*>(x + (size_t)t * HIDDEN);
    const float* A = la + (size_t)idx * RANK * HIDDEN;
    float acc[RANK];
#pragma unroll
    for (int r = 0; r < RANK; r++) acc[r] = 0.f;
    for (int j = threadIdx.x; j < HIDDEN / 4; j += 128) {
        float4 xv = xr[j];
#pragma unroll
        for (int r = 0; r < RANK; r++) {
            float4 av = reinterpret_cast<const float4*>(A + (size_t)r * HIDDEN)[j];
            acc[r] += xv.x * av.x + xv.y * av.y + xv.z * av.z + xv.w * av.w;
        }
    }
#pragma unroll
    for (int r = 0; r < RANK; r++)
#pragma unroll
        for (int o = 16; o > 0; o >>= 1)
            acc[r] += __shfl_xor_sync(0xffffffffu, acc[r], o);

    __shared__ float red[4][RANK];
    int w = threadIdx.x >> 5, l = threadIdx.x & 31;
    if (l == 0)
#pragma unroll
        for (int r = 0; r < RANK; r++) red[w][r] = acc[r];
    __syncthreads();
    if (threadIdx.x < RANK) {
        int r = threadIdx.x;
        float s = red[0][r] + red[1][r] + red[2][r] + red[3][r];
        g_ax[t * RANK + r] = s;
        atomicMax(&g_smax[0], __float_as_uint(fabsf(s)));
    }
}

// ---------------- prep: quantize x -> (h,l) int8, ext cols zero ----------------
__global__ void quant_x_kernel(const float* __restrict__ x) {
    int i = blockIdx.x * blockDim.x + threadIdx.x;          // one 16-col group
    if (i >= TOKENS * (KEXT / 16)) return;
    int row = i / (KEXT / 16);
    int c = (i % (KEXT / 16)) * 16;
    const float inv = 16256.f / __uint_as_float(g_smax[0]);
    int4 hv = {0, 0, 0, 0}, lv = {0, 0, 0, 0};
    if (c < HIDDEN) {
        int8_t* hp = (int8_t*)&hv; int8_t* lp = (int8_t*)&lv;
        const float4* src = reinterpret_cast<const float4*>(x + (size_t)row * HIDDEN + c);
#pragma unroll
        for (int g = 0; g < 4; g++) {
            float4 v = src[g];
            quant15(v.x, inv, hp + g * 4 + 0, lp + g * 4 + 0);
            quant15(v.y, inv, hp + g * 4 + 1, lp + g * 4 + 1);
            quant15(v.z, inv, hp + g * 4 + 2, lp + g * 4 + 2);
            quant15(v.w, inv, hp + g * 4 + 3, lp + g * 4 + 3);
        }
    }
    size_t o = (size_t)row * KEXT + c;
    *reinterpret_cast<int4*>(g_q + QXH + o) = hv;
    *reinterpret_cast<int4*>(g_q + QXL + o) = lv;
}

// ---------------- prep: quantize ax into x ext cols (scatter by idx) ----------------
__global__ void quant_ax_kernel(const void* __restrict__ idx_raw) {
    int i = blockIdx.x * blockDim.x + threadIdx.x;
    if (i >= TOKENS * RANK) return;
    int t = i >> 4, r = i & 15;
    int idx;
    if (g_idx64) idx = (int)((const long long*)idx_raw)[t];
    else         idx = ((const int*)idx_raw)[t];
    if (idx < 0 || idx >= NLORA) return;
    const float inv = 16256.f / __uint_as_float(g_smax[0]);
    int8_t h, l;
    quant15(g_ax[t * RANK + r], inv, &h, &l);
    size_t o = (size_t)t * KEXT + HIDDEN + idx * RANK + r;
    g_q[QXH + o] = h;
    g_q[QXL + o] = l;
}

// ---------------- prep: quantize W + lora_b -> (h,l) int8 ----------------
__global__ void quant_w_kernel(const float* __restrict__ w, const float* __restrict__ lb) {
    int i = blockIdx.x * blockDim.x + threadIdx.x;
    if (i >= OUTDIM * (KEXT / 16)) return;
    int row = i / (KEXT / 16);
    int c = (i % (KEXT / 16)) * 16;
    const float inv = 16256.f / __uint_as_float(g_smax[1]);
    const float4* src;
    if (c < HIDDEN) {
        src = reinterpret_cast<const float4*>(w + (size_t)row * HIDDEN + c);
    } else {
        int l = (c - HIDDEN) >> 4;
        src = reinterpret_cast<const float4*>(lb + ((size_t)l * OUTDIM + row) * RANK);
    }
    int4 hv, lv;
    int8_t* hp = (int8_t*)&hv; int8_t* lp = (int8_t*)&lv;
#pragma unroll
    for (int g = 0; g < 4; g++) {
        float4 v = src[g];
        quant15(v.x, inv, hp + g * 4 + 0, lp + g * 4 + 0);
        quant15(v.y, inv, hp + g * 4 + 1, lp + g * 4 + 1);
        quant15(v.z, inv, hp + g * 4 + 2, lp + g * 4 + 2);
        quant15(v.w, inv, hp + g * 4 + 3, lp + g * 4 + 3);
    }
    size_t o = (size_t)row * KEXT + c;
    *reinterpret_cast<int4*>(g_q + QWH + o) = hv;
    *reinterpret_cast<int4*>(g_q + QWL + o) = lv;
}

// ---------------- main GEMM (int8 hi/lo, 3 terms, exact int32 accum) ----------------
__global__ void __launch_bounds__(512, 1)
gemm_kernel(const float* __restrict__ bias, float* __restrict__ out) {
    extern __shared__ char smem[];
    const uint32_t sb = smem_u32(smem);
    const int tid = threadIdx.x;
    const int lane = tid & 31, wid = tid >> 5;
    const int wm = wid >> 2, wn = wid & 3;                  // 4x4 warps, tile 64x16
    const int m0 = (int)(blockIdx.x & 7) * BM;
    const int n0 = (int)(blockIdx.x >> 3) * BN;

    // cp.async slots: 2560 16B segs / 512 threads = 5 each
    uint32_t goff[5], soff[5];
#pragma unroll
    for (int j = 0; j < 5; j++) {
        int s = tid + j * 512;
        int row = s >> 2, seg = s & 3;
        uint32_t base, loc, grow;
        if (row < 256)      { base = QXH; grow = m0 + row;       loc = OFF_AHI + row * STRIDE; }
        else if (row < 512) { base = QXL; grow = m0 + row - 256; loc = OFF_ALO + (row - 256) * STRIDE; }
        else if (row < 576) { base = QWH; grow = n0 + row - 512; loc = OFF_BHI + (row - 512) * STRIDE; }
        else                { base = QWL; grow = n0 + row - 576; loc = OFF_BLO + (row - 576) * STRIDE; }
        goff[j] = base + grow * (uint32_t)KEXT + (uint32_t)seg * 16;
        soff[j] = loc + (uint32_t)seg * 16;
    }

    // ldmatrix lane bases
    const uint32_t a_base = (uint32_t)(wm * 64 + (lane & 15)) * STRIDE + ((lane >> 4) << 4);
    const uint32_t b_base = (uint32_t)(wn * 16 + ((lane >> 4) << 3) + (lane & 7)) * STRIDE
                          + (uint32_t)(((lane >> 3) & 1) << 4);

    int hh[4][2][4], mid[4][2][4];
#pragma unroll
    for (int a = 0; a < 4; a++)
#pragma unroll
        for (int b = 0; b < 2; b++)
#pragma unroll
            for (int c = 0; c < 4; c++) { hh[a][b][c] = 0; mid[a][b][c] = 0; }

    // prologue: stages 0, 1
#pragma unroll
    for (int p = 0; p < 2; p++) {
        uint32_t s0 = sb + (uint32_t)p * STG;
#pragma unroll
        for (int j = 0; j < 5; j++)
            cp16(s0 + soff[j], g_q + goff[j] + p * BK);
        CP_COMMIT();
    }

#pragma unroll 1
    for (int ks = 0; ks < NCH; ks++) {
        const uint32_t s0 = sb + (uint32_t)(ks % 3) * STG;
        if (ks < NCH - 1) asm volatile("cp.async.wait_group 1;" ::: "memory");
        else              asm volatile("cp.async.wait_group 0;" ::: "memory");
        __syncthreads();

        if (ks + 2 < NCH) {
            const uint32_t sl = sb + (uint32_t)((ks + 2) % 3) * STG;
            const uint32_t kadd = (uint32_t)(ks + 2) * BK;
#pragma unroll
            for (int j = 0; j < 5; j++)
                cp16(sl + soff[j], g_q + goff[j] + kadd);
            CP_COMMIT();
        }

#pragma unroll
        for (int k32 = 0; k32 < 2; k32++) {
            const uint32_t ko = (uint32_t)k32 * 32;
            uint32_t bh[4], bl[4];
            LDSM4(bh, s0 + OFF_BHI + b_base + ko);
            LDSM4(bl, s0 + OFF_BLO + b_base + ko);
#pragma unroll
            for (int mt = 0; mt < 4; mt++) {
                uint32_t ah[4], al[4];
                LDSM4(ah, s0 + OFF_AHI + a_base + (uint32_t)mt * 16 * STRIDE + ko);
                LDSM4(al, s0 + OFF_ALO + a_base + (uint32_t)mt * 16 * STRIDE + ko);
#pragma unroll
                for (int ng = 0; ng < 2; ng++) {
                    imma(hh[mt][ng],  ah, bh[2 * ng], bh[2 * ng + 1]);
                    imma(mid[mt][ng], ah, bl[2 * ng], bl[2 * ng + 1]);
                    imma(mid[mt][ng], al, bh[2 * ng], bh[2 * ng + 1]);
                }
            }
        }
    }

    // epilogue
    const float sx = __uint_as_float(g_smax[0]) * (1.f / 16256.f);
    const float sw = __uint_as_float(g_smax[1]) * (1.f / 16256.f);
    const float s2 = sx * sw;
    const int r_base = m0 + wm * 64 + (lane >> 2);
    const int c_base = n0 + wn * 16 + (lane & 3) * 2;
#pragma unroll
    for (int mt = 0; mt < 4; mt++) {
#pragma unroll
        for (int ng = 0; ng < 2; ng++) {
            const int r0 = r_base + mt * 16;
            const int c = c_base + ng * 8;
            float2 bv = *reinterpret_cast<const float2*>(bias + c);
            float2 v0, v1;
            v0.x = s2 * (16384.f * (float)hh[mt][ng][0] + 128.f * (float)mid[mt][ng][0]) + bv.x;
            v0.y = s2 * (16384.f * (float)hh[mt][ng][1] + 128.f * (float)mid[mt][ng][1]) + bv.y;
            v1.x = s2 * (16384.f * (float)hh[mt][ng][2] + 128.f * (float)mid[mt][ng][2]) + bv.x;
            v1.y = s2 * (16384.f * (float)hh[mt][ng][3] + 128.f * (float)mid[mt][ng][3]) + bv.y;
            *reinterpret_cast<float2*>(out + (size_t)r0 * OUTDIM + c) = v0;
            *reinterpret_cast<float2*>(out + (size_t)(r0 + 8) * OUTDIM + c) = v1;
        }
    }
}

// ---------------- launch ----------------
extern "C" void kernel_launch(void* const* d_in, const int* in_sizes, int n_in,
                              void* d_out, int out_size) {
    const float* x      = (const float*)d_in[0];
    const float* weight = (const float*)d_in[1];
    const float* bias   = (const float*)d_in[2];
    const float* lora_a = (const float*)d_in[3];
    const float* lora_b = (const float*)d_in[4];
    const void*  indices = d_in[5];
    float* out = (float*)d_out;

    cudaFuncSetAttribute(gemm_kernel, cudaFuncAttributeMaxDynamicSharedMemorySize, SMEM_BYTES);

    init_kernel<<<1, 32>>>();
    detect_kernel<<<1, 256>>>((const int*)indices);
    maxabs_kernel<<<256, 256>>>((const float4*)x, TOKENS * HIDDEN / 4, 0);
    maxabs_kernel<<<256, 256>>>((const float4*)weight, OUTDIM * HIDDEN / 4, 1);
    maxabs_kernel<<<64, 256>>>((const float4*)lora_b, NLORA * OUTDIM * RANK / 4, 1);
    lora_proj_kernel<<<TOKENS, 128>>>(x, lora_a, indices);
    quant_x_kernel<<<(TOKENS * (KEXT / 16) + 255) / 256, 256>>>(x);
    quant_ax_kernel<<<(TOKENS * RANK + 255) / 256, 256>>>(indices);
    quant_w_kernel<<<(OUTDIM * (KEXT / 16) + 255) / 256, 256>>>(weight, lora_b);
    gemm_kernel<<<(TOKENS / BM) * (OUTDIM / BN), 512, SMEM_BYTES>>>(bias, out);
}

// round 9
// speedup vs baseline: 5.1717x; 5.1717x over previous
#include <cuda_runtime.h>
#include <cuda_fp16.h>
#include <cstdint>

#define TOKENS 2048
#define HIDDEN 4096
#define OUTDIM 4096
#define NLORA  16
#define RANK   16
#define KEXT   (HIDDEN + NLORA * RANK)   // 4352

#define BM 256
#define BN 128
#define BK 32
#define NCH (KEXT / BK)                  // 136

#define STRIDE 80                        // 64B data + 16B pad (conflict-free ldmatrix)
#define OFF_A 0
#define OFF_B (BM * STRIDE)              // 20480
#define STG   ((BM + BN) * STRIDE)       // 30720
#define SMEM_BYTES (3 * STG)             // 92160

static_assert(KEXT % BK == 0, "");

__device__ __align__(16) __half g_x[(size_t)TOKENS * KEXT];
__device__ __align__(16) __half g_w[(size_t)OUTDIM * KEXT];
__device__ int g_idx64;

// ---------------- helpers ----------------
__device__ __forceinline__ uint32_t smem_u32(const void* p) {
    uint32_t a;
    asm("{ .reg .u64 t; cvta.to.shared.u64 t, %1; cvt.u32.u64 %0, t; }" : "=r"(a) : "l"(p));
    return a;
}
__device__ __forceinline__ void cp16(uint32_t sdst, const void* gsrc) {
    asm volatile("cp.async.cg.shared.global [%0], [%1], 16;" :: "r"(sdst), "l"(gsrc) : "memory");
}
#define CP_COMMIT() asm volatile("cp.async.commit_group;" ::: "memory")

#define LDSM4(r, a) \
    asm volatile("ldmatrix.sync.aligned.m8n8.x4.shared.b16 {%0,%1,%2,%3}, [%4];" \
        : "=r"((r)[0]), "=r"((r)[1]), "=r"((r)[2]), "=r"((r)[3]) : "r"(a))

__device__ __forceinline__ void mma16816(float* c, const uint32_t* a, uint32_t b0, uint32_t b1) {
    asm volatile(
        "mma.sync.aligned.m16n8k16.row.col.f32.f16.f16.f32 "
        "{%0,%1,%2,%3}, {%4,%5,%6,%7}, {%8,%9}, {%0,%1,%2,%3};"
        : "+f"(c[0]), "+f"(c[1]), "+f"(c[2]), "+f"(c[3])
        : "r"(a[0]), "r"(a[1]), "r"(a[2]), "r"(a[3]), "r"(b0), "r"(b1));
}

// ---------------- prep: detect int32 vs int64 indices ----------------
__global__ void detect_kernel(const int* __restrict__ w) {
    __shared__ int any;
    if (threadIdx.x == 0) any = 0;
    __syncthreads();
    for (int i = threadIdx.x * 2 + 1; i < TOKENS; i += 2 * blockDim.x)
        if (w[i] != 0) any = 1;
    __syncthreads();
    if (threadIdx.x == 0) g_idx64 = (any == 0) ? 1 : 0;
}

// ---------------- prep: x -> fp16, LoRA-ext cols zeroed ----------------
__global__ void convert_x_kernel(const float* __restrict__ x) {
    int i = blockIdx.x * blockDim.x + threadIdx.x;   // one 8-col group
    if (i >= TOKENS * (KEXT / 8)) return;
    int row = i / (KEXT / 8);
    int c = (i % (KEXT / 8)) * 8;
    __half h[8];
    if (c < HIDDEN) {
        const float4* src = reinterpret_cast<const float4*>(x + (size_t)row * HIDDEN + c);
        float4 v0 = src[0], v1 = src[1];
        h[0] = __float2half(v0.x); h[1] = __float2half(v0.y);
        h[2] = __float2half(v0.z); h[3] = __float2half(v0.w);
        h[4] = __float2half(v1.x); h[5] = __float2half(v1.y);
        h[6] = __float2half(v1.z); h[7] = __float2half(v1.w);
    } else {
#pragma unroll
        for (int j = 0; j < 8; j++) h[j] = __float2half(0.f);
    }
    *reinterpret_cast<int4*>(g_x + (size_t)row * KEXT + c) = *reinterpret_cast<int4*>(h);
}

// ---------------- prep: W -> fp16, lora_b packed into ext cols ----------------
__global__ void convert_w_kernel(const float* __restrict__ w, const float* __restrict__ lb) {
    int i = blockIdx.x * blockDim.x + threadIdx.x;
    if (i >= OUTDIM * (KEXT / 8)) return;
    int row = i / (KEXT / 8);
    int c = (i % (KEXT / 8)) * 8;
    const float4* src;
    if (c < HIDDEN) {
        src = reinterpret_cast<const float4*>(w + (size_t)row * HIDDEN + c);
    } else {
        int cc = c - HIDDEN;
        int l = cc >> 4, r = cc & 15;    // r = 0 or 8
        src = reinterpret_cast<const float4*>(lb + ((size_t)l * OUTDIM + row) * RANK + r);
    }
    float4 v0 = src[0], v1 = src[1];
    __half h[8];
    h[0] = __float2half(v0.x); h[1] = __float2half(v0.y);
    h[2] = __float2half(v0.z); h[3] = __float2half(v0.w);
    h[4] = __float2half(v1.x); h[5] = __float2half(v1.y);
    h[6] = __float2half(v1.z); h[7] = __float2half(v1.w);
    *reinterpret_cast<int4*>(g_w + (size_t)row * KEXT + c) = *reinterpret_cast<int4*>(h);
}

// ---------------- prep: per-token rank-16 projection -> scattered ext cols ----------------
__global__ void lora_proj_kernel(const float* __restrict__ x,
                                 const float* __restrict__ la,
                                 const void* __restrict__ idx_raw) {
    const int t = blockIdx.x;
    int idx;
    if (g_idx64) idx = (int)((const long long*)idx_raw)[t];
    else         idx = ((const int*)idx_raw)[t];
    if (idx < 0 || idx >= NLORA) return;

    const float4* xr = reinterpret_cast<const float4*>(x + (size_t)t * HIDDEN);
    const float* A = la + (size_t)idx * RANK * HIDDEN;
    float acc[RANK];
#pragma unroll
    for (int r = 0; r < RANK; r++) acc[r] = 0.f;
    for (int j = threadIdx.x; j < HIDDEN / 4; j += 128) {
        float4 xv = xr[j];
#pragma unroll
        for (int r = 0; r < RANK; r++) {
            float4 av = reinterpret_cast<const float4*>(A + (size_t)r * HIDDEN)[j];
            acc[r] += xv.x * av.x + xv.y * av.y + xv.z * av.z + xv.w * av.w;
        }
    }
#pragma unroll
    for (int r = 0; r < RANK; r++)
#pragma unroll
        for (int o = 16; o > 0; o >>= 1)
            acc[r] += __shfl_xor_sync(0xffffffffu, acc[r], o);

    __shared__ float red[4][RANK];
    int w = threadIdx.x >> 5, l = threadIdx.x & 31;
    if (l == 0)
#pragma unroll
        for (int r = 0; r < RANK; r++) red[w][r] = acc[r];
    __syncthreads();
    if (threadIdx.x < RANK) {
        int r = threadIdx.x;
        float s = red[0][r] + red[1][r] + red[2][r] + red[3][r];
        g_x[(size_t)t * KEXT + HIDDEN + idx * RANK + r] = __float2half(s);
    }
}

// ---------------- main GEMM: out = x_f16 @ w_f16^T (fp32 accum) + bias ----------------
__global__ void __launch_bounds__(512, 1)
gemm_kernel(const float* __restrict__ bias, float* __restrict__ out) {
    extern __shared__ char smem[];
    const uint32_t sb = smem_u32(smem);
    const int tid = threadIdx.x;
    const int lane = tid & 31, wid = tid >> 5;
    const int wm = wid >> 2, wn = wid & 3;          // 4 x 4 warps, warp tile 64 x 32
    const int m0 = (int)(blockIdx.x & 7) * BM;
    const int n0 = (int)(blockIdx.x >> 3) * BN;

    // cp.async slots: 384 rows x 4 segs = 1536 / 512 threads = 3 each
    uint32_t goff[3], soff[3];
#pragma unroll
    for (int j = 0; j < 3; j++) {
        int s = tid + j * 512;
        int row = s >> 2, seg = s & 3;
        const __half* base;
        uint32_t loc, grow;
        if (row < 256) { base = g_x; grow = m0 + row;       loc = OFF_A + row * STRIDE; }
        else           { base = g_w; grow = n0 + row - 256; loc = OFF_B + (row - 256) * STRIDE; }
        goff[j] = grow * (uint32_t)KEXT + (uint32_t)seg * 8;
        soff[j] = loc + (uint32_t)seg * 16;
        (void)base;
    }
    const __half* gbase[3];
#pragma unroll
    for (int j = 0; j < 3; j++) {
        int s = tid + j * 512;
        gbase[j] = ((s >> 2) < 256) ? g_x : g_w;
    }

    // ldmatrix lane base offsets (within a stage)
    const uint32_t a_base = (uint32_t)(wm * 64 + (lane & 15)) * STRIDE + ((lane >> 4) << 4);
    const uint32_t b_base = (uint32_t)(wn * 32 + (lane & 15)) * STRIDE + ((lane >> 4) << 4);

    float acc[4][4][4];
#pragma unroll
    for (int a = 0; a < 4; a++)
#pragma unroll
        for (int b = 0; b < 4; b++)
#pragma unroll
            for (int c = 0; c < 4; c++) acc[a][b][c] = 0.f;

    // prologue: stages 0 and 1
#pragma unroll
    for (int p = 0; p < 2; p++) {
        uint32_t s0 = sb + (uint32_t)p * STG;
#pragma unroll
        for (int j = 0; j < 3; j++)
            cp16(s0 + soff[j], gbase[j] + goff[j] + p * BK);
        CP_COMMIT();
    }

#pragma unroll 1
    for (int ks = 0; ks < NCH; ks++) {
        const uint32_t s0 = sb + (uint32_t)(ks % 3) * STG;
        if (ks < NCH - 1) asm volatile("cp.async.wait_group 1;" ::: "memory");
        else              asm volatile("cp.async.wait_group 0;" ::: "memory");
        __syncthreads();

        if (ks + 2 < NCH) {
            const uint32_t sl = sb + (uint32_t)((ks + 2) % 3) * STG;
            const uint32_t kadd = (uint32_t)(ks + 2) * BK;
#pragma unroll
            for (int j = 0; j < 3; j++)
                cp16(sl + soff[j], gbase[j] + goff[j] + kadd);
            CP_COMMIT();
        }

#pragma unroll
        for (int k16 = 0; k16 < 2; k16++) {
            const uint32_t koff = (uint32_t)k16 * 32;
            uint32_t bh[8];
            LDSM4(bh + 0, s0 + OFF_B + b_base + koff);
            LDSM4(bh + 4, s0 + OFF_B + b_base + 16 * STRIDE + koff);
#pragma unroll
            for (int mt = 0; mt < 4; mt++) {
                uint32_t ah[4];
                LDSM4(ah, s0 + OFF_A + a_base + (uint32_t)mt * 16 * STRIDE + koff);
#pragma unroll
                for (int j = 0; j < 4; j++) {
                    const int g = (j >> 1) * 4 + (j & 1);
                    mma16816(acc[mt][j], ah, bh[g], bh[g + 2]);
                }
            }
        }
    }

    // epilogue: acc + bias -> out
    const int orow = m0 + wm * 64 + (lane >> 2);
    const int ocol = n0 + wn * 32 + (lane & 3) * 2;
#pragma unroll
    for (int mt = 0; mt < 4; mt++) {
#pragma unroll
        for (int j = 0; j < 4; j++) {
            const int r0 = orow + mt * 16;
            const int c = ocol + j * 8;
            float2 bv = *reinterpret_cast<const float2*>(bias + c);
            float2 v0, v1;
            v0.x = acc[mt][j][0] + bv.x; v0.y = acc[mt][j][1] + bv.y;
            v1.x = acc[mt][j][2] + bv.x; v1.y = acc[mt][j][3] + bv.y;
            *reinterpret_cast<float2*>(out + (size_t)r0 * OUTDIM + c) = v0;
            *reinterpret_cast<float2*>(out + (size_t)(r0 + 8) * OUTDIM + c) = v1;
        }
    }
}

// ---------------- launch ----------------
extern "C" void kernel_launch(void* const* d_in, const int* in_sizes, int n_in,
                              void* d_out, int out_size) {
    const float* x      = (const float*)d_in[0];
    const float* weight = (const float*)d_in[1];
    const float* bias   = (const float*)d_in[2];
    const float* lora_a = (const float*)d_in[3];
    const float* lora_b = (const float*)d_in[4];
    const void*  indices = d_in[5];
    float* out = (float*)d_out;

    cudaFuncSetAttribute(gemm_kernel, cudaFuncAttributeMaxDynamicSharedMemorySize, SMEM_BYTES);

    detect_kernel<<<1, 256>>>((const int*)indices);
    convert_x_kernel<<<(TOKENS * (KEXT / 8)) / 256, 256>>>(x);
    convert_w_kernel<<<(OUTDIM * (KEXT / 8)) / 256, 256>>>(weight, lora_b);
    lora_proj_kernel<<<TOKENS, 128>>>(x, lora_a, indices);
    gemm_kernel<<<(TOKENS / BM) * (OUTDIM / BN), 512, SMEM_BYTES>>>(bias, out);
}